// round 4
// baseline (speedup 1.0000x reference)
#include <cuda_runtime.h>
#include <cuda_bf16.h>
#include <math.h>
#include <cstdint>

#define B_SZ   2
#define LSEQ   1024
#define DMODEL 1024
#define DIN    2048
#define NST    16
#define DTR    64
#define MROWS  (B_SZ*LSEQ)   /* 2048 */

// ---------------- scratch (device globals; no allocation allowed) ------------
__device__ float g_XZ[MROWS*8192];              // [m][dir*4096 + (xi | z)]
__device__ float g_U [MROWS*4096];              // fp32 for scan
__device__ __nv_bfloat16 g_Uh[MROWS*4096],  g_Ul[MROWS*4096];
__device__ __nv_bfloat16 g_Xh[MROWS*DMODEL], g_Xl[MROWS*DMODEL];
__device__ __nv_bfloat16 g_Winh[8192*DMODEL], g_Winl[8192*DMODEL];
__device__ __nv_bfloat16 g_Xph[256*DIN],    g_Xpl[256*DIN];      // padded xpW
__device__ float g_XDBLP[4*MROWS*256];
__device__ float g_XDBL[MROWS*256];
__device__ __nv_bfloat16 g_XDh[MROWS*256],  g_XDl[MROWS*256];
__device__ __nv_bfloat16 g_dtWh[4096*DTR],  g_dtWl[4096*DTR];    // dir-concat rows
__device__ float g_DELTA[(size_t)MROWS*4096];
__device__ __nv_bfloat16 g_YGh[MROWS*4096], g_YGl[MROWS*4096];
__device__ __nv_bfloat16 g_Wouth[DMODEL*4096], g_Woutl[DMODEL*4096]; // K-concat cols

// ======================= helpers =============================================
__device__ __forceinline__ uint32_t smem_u32(const void* p) {
    uint32_t a;
    asm("{ .reg .u64 t; cvta.to.shared.u64 t, %1; cvt.u32.u64 %0, t; }" : "=r"(a) : "l"(p));
    return a;
}
#define LDM4(r0,r1,r2,r3,addr)                                                      \
    asm volatile("ldmatrix.sync.aligned.m8n8.x4.shared.b16 {%0,%1,%2,%3}, [%4];"    \
        : "=r"(r0),"=r"(r1),"=r"(r2),"=r"(r3) : "r"(addr))
#define MMA16816(c,a,b)                                                             \
    asm volatile("mma.sync.aligned.m16n8k16.row.col.f32.bf16.bf16.f32 "             \
        "{%0,%1,%2,%3}, {%4,%5,%6,%7}, {%8,%9}, {%0,%1,%2,%3};"                     \
        : "+f"((c)[0]),"+f"((c)[1]),"+f"((c)[2]),"+f"((c)[3])                       \
        : "r"((a)[0]),"r"((a)[1]),"r"((a)[2]),"r"((a)[3]),"r"((b)[0]),"r"((b)[1]))
#define CPA16(dst, src) asm volatile("cp.async.cg.shared.global [%0], [%1], 16;" :: "r"(dst), "l"(src) : "memory")
#define CPCOMMIT()      asm volatile("cp.async.commit_group;" ::: "memory")
#define CPWAIT0()       asm volatile("cp.async.wait_group 0;" ::: "memory")
#define CPWAIT1()       asm volatile("cp.async.wait_group 1;" ::: "memory")

__device__ __forceinline__ void split1(float v, __nv_bfloat16& h, __nv_bfloat16& l) {
    h = __float2bfloat16(v);
    l = __float2bfloat16(v - __bfloat162float(h));
}

// ======================= HMMA GEMM (pre-split bf16 hi/lo planes) =============
// C[M,N] = A[M,K]*B[N,K]^T, fp32 via hi*hi + hi*lo + lo*hi.
// A gets +a_off1 (elements) when CTA n-tile >= nsplit (dir-dependent A slice).
// kz>0: split-K over blockIdx.z; C offset by z*M*ldc (partials).
// EPI: 0 = store, 1 = softplus(acc + bias[n]) (bias0/bias1 split at nsplit),
//      2 = store alpha*acc
#define BKC 32
#define ASTRIDE 80             /* bytes per smem row: 32 bf16 + 8 pad */
#define STG_A_HI 0
#define STG_A_LO 10240
#define STG_B_HI 20480
#define STG_B_LO 30720
#define STG_STRIDE 40960
#define HG_SMEM (2*STG_STRIDE)

template<int EPI>
__global__ __launch_bounds__(256, 1) void hgemm(
    const __nv_bfloat16* __restrict__ Ah, const __nv_bfloat16* __restrict__ Al,
    int lda, int a_off1, int nsplit,
    const __nv_bfloat16* __restrict__ Bh, const __nv_bfloat16* __restrict__ Bl,
    int ldb,
    float* __restrict__ C, int ldc, int K,
    const float* __restrict__ bias0, const float* __restrict__ bias1,
    float alpha, int kz)
{
    extern __shared__ char sm[];
    const uint32_t smb = smem_u32(sm);
    const int tid = threadIdx.x;
    const int bm = blockIdx.y * 128, bn = blockIdx.x * 128;
    if (kz > 0) {
        Ah += (size_t)blockIdx.z * kz;  Al += (size_t)blockIdx.z * kz;
        Bh += (size_t)blockIdx.z * kz;  Bl += (size_t)blockIdx.z * kz;
        C  += (size_t)blockIdx.z * (size_t)(gridDim.y * 128) * (size_t)ldc;
        K = kz;
    }
    const int aoff = (nsplit && bn >= nsplit) ? a_off1 : 0;

    // ---- producer: each thread owns 2x16B per plane per chunk ---------------
    const int grow = tid >> 1;               // 0..127
    const int seg  = (tid & 1) << 1;         // 0 or 2 (16B units within 64B row)
    const char* gAh = (const char*)(Ah + aoff + (size_t)(bm + grow) * lda);
    const char* gAl = (const char*)(Al + aoff + (size_t)(bm + grow) * lda);
    const char* gBh = (const char*)(Bh + (size_t)(bn + grow) * ldb);
    const char* gBl = (const char*)(Bl + (size_t)(bn + grow) * ldb);
    const uint32_t srow = smb + (uint32_t)(grow * ASTRIDE + seg * 16);

    // ---- warp geometry ------------------------------------------------------
    const int wid = tid >> 5, lane = tid & 31;
    const int wm = (wid >> 2) * 64;
    const int wn = (wid & 3) * 32;
    const int tq = lane >> 2, tr = lane & 3;
    const uint32_t aoffm = (uint32_t)((wm + (lane & 15)) * ASTRIDE + ((lane >> 4) << 4));
    const int g = lane >> 3;
    const uint32_t boffm = (uint32_t)((wn + ((g >> 1) << 3) + (lane & 7)) * ASTRIDE + ((g & 1) << 4));

    float acc[4][4][4];
#pragma unroll
    for (int i = 0; i < 4; i++)
#pragma unroll
        for (int j = 0; j < 4; j++)
#pragma unroll
            for (int q = 0; q < 4; q++) acc[i][j][q] = 0.f;

    const int nch = K / BKC;

    auto issue = [&](int s) {
        const uint32_t st = srow + (uint32_t)(s & 1) * STG_STRIDE;
        const int go = s * (BKC * 2) + seg * 16;     // byte offset in gmem row
        CPA16(st + STG_A_HI,      gAh + go);
        CPA16(st + STG_A_HI + 16, gAh + go + 16);
        CPA16(st + STG_A_LO,      gAl + go);
        CPA16(st + STG_A_LO + 16, gAl + go + 16);
        CPA16(st + STG_B_HI,      gBh + go);
        CPA16(st + STG_B_HI + 16, gBh + go + 16);
        CPA16(st + STG_B_LO,      gBl + go);
        CPA16(st + STG_B_LO + 16, gBl + go + 16);
        CPCOMMIT();
    };

    issue(0);
    for (int s = 0; s < nch; s++) {
        if (s + 1 < nch) { issue(s + 1); CPWAIT1(); }
        else             { CPWAIT0(); }
        __syncthreads();
        const uint32_t sa = smb + (uint32_t)(s & 1) * STG_STRIDE;
#pragma unroll
        for (int ph = 0; ph < 2; ph++) {
            const uint32_t ka = sa + ph * 32;        // +16 bf16 per k-phase
            uint32_t ah[4][4], al[4][4], bh[4][2], bl[4][2];
#pragma unroll
            for (int i = 0; i < 4; i++)
                LDM4(ah[i][0], ah[i][1], ah[i][2], ah[i][3], ka + STG_A_HI + aoffm + i*(16*ASTRIDE));
#pragma unroll
            for (int i = 0; i < 4; i++)
                LDM4(al[i][0], al[i][1], al[i][2], al[i][3], ka + STG_A_LO + aoffm + i*(16*ASTRIDE));
            LDM4(bh[0][0], bh[0][1], bh[1][0], bh[1][1], ka + STG_B_HI + boffm);
            LDM4(bh[2][0], bh[2][1], bh[3][0], bh[3][1], ka + STG_B_HI + boffm + 16*ASTRIDE);
            LDM4(bl[0][0], bl[0][1], bl[1][0], bl[1][1], ka + STG_B_LO + boffm);
            LDM4(bl[2][0], bl[2][1], bl[3][0], bl[3][1], ka + STG_B_LO + boffm + 16*ASTRIDE);
#pragma unroll
            for (int i = 0; i < 4; i++)
#pragma unroll
                for (int j = 0; j < 4; j++) {
                    MMA16816(acc[i][j], ah[i], bh[j]);
                    MMA16816(acc[i][j], ah[i], bl[j]);
                    MMA16816(acc[i][j], al[i], bh[j]);
                }
        }
        __syncthreads();
    }

    // ---- epilogue -----------------------------------------------------------
    const float* bias = nullptr;
    if (EPI == 1) bias = (nsplit && bn >= nsplit) ? (bias1 - nsplit) : bias0;
#pragma unroll
    for (int i = 0; i < 4; i++) {
        const int row0 = bm + wm + 16*i + tq;
#pragma unroll
        for (int j = 0; j < 4; j++) {
            const int col = bn + wn + 8*j + 2*tr;
            float v0 = acc[i][j][0], v1 = acc[i][j][1];
            float v2 = acc[i][j][2], v3 = acc[i][j][3];
            if (EPI == 1) {
                const float b0v = bias[col], b1v = bias[col+1];
                v0 += b0v; v1 += b1v; v2 += b0v; v3 += b1v;
                v0 = (v0 > 20.f) ? v0 : log1pf(__expf(v0));
                v1 = (v1 > 20.f) ? v1 : log1pf(__expf(v1));
                v2 = (v2 > 20.f) ? v2 : log1pf(__expf(v2));
                v3 = (v3 > 20.f) ? v3 : log1pf(__expf(v3));
            } else if (EPI == 2) {
                v0 *= alpha; v1 *= alpha; v2 *= alpha; v3 *= alpha;
            }
            *reinterpret_cast<float2*>(C + (size_t)row0 * ldc + col)       = make_float2(v0, v1);
            *reinterpret_cast<float2*>(C + (size_t)(row0 + 8) * ldc + col) = make_float2(v2, v3);
        }
    }
}

// ======================= convert kernels =====================================
__global__ __launch_bounds__(256) void cvt_plane(
    const float* __restrict__ src, __nv_bfloat16* __restrict__ hi,
    __nv_bfloat16* __restrict__ lo, int n4)
{
    const int i = blockIdx.x * 256 + threadIdx.x;
    if (i >= n4) return;
    float4 v = reinterpret_cast<const float4*>(src)[i];
    __nv_bfloat16 h0,h1,h2,h3,l0,l1,l2,l3;
    split1(v.x,h0,l0); split1(v.y,h1,l1); split1(v.z,h2,l2); split1(v.w,h3,l3);
    reinterpret_cast<__nv_bfloat162*>(hi)[2*i]   = __nv_bfloat162(h0,h1);
    reinterpret_cast<__nv_bfloat162*>(hi)[2*i+1] = __nv_bfloat162(h2,h3);
    reinterpret_cast<__nv_bfloat162*>(lo)[2*i]   = __nv_bfloat162(l0,l1);
    reinterpret_cast<__nv_bfloat162*>(lo)[2*i+1] = __nv_bfloat162(l2,l3);
}

// xpW -> [256][2048]: rows 0-95 f, 96-127 zero, 128-223 b, 224-255 zero
__global__ __launch_bounds__(256) void cvt_xp(
    const float* __restrict__ f, const float* __restrict__ b)
{
    const int i = blockIdx.x * 256 + threadIdx.x;     // over 256*2048/4
    const int idx = i * 4;
    const int r = idx >> 11, c = idx & 2047;
    float4 v = make_float4(0.f,0.f,0.f,0.f);
    if (r < 96)                 v = *reinterpret_cast<const float4*>(f + r*2048 + c);
    else if (r >= 128 && r < 224) v = *reinterpret_cast<const float4*>(b + (r-128)*2048 + c);
    __nv_bfloat16 h0,h1,h2,h3,l0,l1,l2,l3;
    split1(v.x,h0,l0); split1(v.y,h1,l1); split1(v.z,h2,l2); split1(v.w,h3,l3);
    reinterpret_cast<__nv_bfloat162*>(g_Xph)[2*i]   = __nv_bfloat162(h0,h1);
    reinterpret_cast<__nv_bfloat162*>(g_Xph)[2*i+1] = __nv_bfloat162(h2,h3);
    reinterpret_cast<__nv_bfloat162*>(g_Xpl)[2*i]   = __nv_bfloat162(l0,l1);
    reinterpret_cast<__nv_bfloat162*>(g_Xpl)[2*i+1] = __nv_bfloat162(l2,l3);
}

// outW K-concat -> [1024][4096]: cols<2048 from f, else b
__global__ __launch_bounds__(256) void cvt_out(
    const float* __restrict__ f, const float* __restrict__ b)
{
    const int i = blockIdx.x * 256 + threadIdx.x;     // over 1024*4096/4
    const int idx = i * 4;
    const int r = idx >> 12, c = idx & 4095;
    float4 v = (c < 2048)
        ? *reinterpret_cast<const float4*>(f + (size_t)r*2048 + c)
        : *reinterpret_cast<const float4*>(b + (size_t)r*2048 + (c - 2048));
    __nv_bfloat16 h0,h1,h2,h3,l0,l1,l2,l3;
    split1(v.x,h0,l0); split1(v.y,h1,l1); split1(v.z,h2,l2); split1(v.w,h3,l3);
    reinterpret_cast<__nv_bfloat162*>(g_Wouth)[2*i]   = __nv_bfloat162(h0,h1);
    reinterpret_cast<__nv_bfloat162*>(g_Wouth)[2*i+1] = __nv_bfloat162(h2,h3);
    reinterpret_cast<__nv_bfloat162*>(g_Woutl)[2*i]   = __nv_bfloat162(l0,l1);
    reinterpret_cast<__nv_bfloat162*>(g_Woutl)[2*i+1] = __nv_bfloat162(l2,l3);
}

// ------------- depthwise conv + SiLU; writes fp32 U and bf16 planes ----------
__global__ __launch_bounds__(256) void conv_silu_kernel(
    const float* __restrict__ convW_f, const float* __restrict__ convB_f,
    const float* __restrict__ convW_b, const float* __restrict__ convB_b)
{
    const int i = blockIdx.x * 256 + threadIdx.x;   // over MROWS*4096
    const int c = i & 4095;
    const int row = i >> 12;
    const int l = row & (LSEQ - 1);
    const int b = row >> 10;
    const int dir = c >> 11;
    const int d = c & (DIN - 1);
    const float* w = (dir ? convW_b : convW_f) + d*4;
    float acc = (dir ? convB_b : convB_f)[d];
    const float* xi = g_XZ + dir*4096 + d;
    if (dir == 0) {
#pragma unroll
        for (int k = 0; k < 4; k++) {
            int ls = l - 3 + k;
            if (ls >= 0) acc = fmaf(w[k], xi[(size_t)(b*LSEQ + ls)*8192], acc);
        }
    } else {
#pragma unroll
        for (int k = 0; k < 4; k++) {
            int ls = l + 3 - k;
            if (ls < LSEQ) acc = fmaf(w[k], xi[(size_t)(b*LSEQ + ls)*8192], acc);
        }
    }
    const float sig = 1.f / (1.f + __expf(-acc));
    const float u = acc * sig;
    const size_t o = (size_t)row*4096 + c;
    g_U[o] = u;
    __nv_bfloat16 h, lo2; split1(u, h, lo2);
    g_Uh[o] = h; g_Ul[o] = lo2;
}

// ------------------------- split-K reduce + plane split ----------------------
__global__ __launch_bounds__(256) void reduce_xdbl_kernel()
{
    const int i = blockIdx.x * 256 + threadIdx.x;   // over MROWS*256
    float s = 0.f;
#pragma unroll
    for (int k = 0; k < 4; k++) s += g_XDBLP[(size_t)k*MROWS*256 + i];
    g_XDBL[i] = s;
    __nv_bfloat16 h, l; split1(s, h, l);
    g_XDh[i] = h; g_XDl[i] = l;
}

// ------------------- selective scan + gating; writes YG planes ---------------
__global__ __launch_bounds__(256) void scan_kernel(
    const float* __restrict__ Alog_f, const float* __restrict__ Alog_b,
    const float* __restrict__ Dp_f,  const float* __restrict__ Dp_b)
{
    const int dir = blockIdx.z;
    const int b   = blockIdx.y;
    const int d0  = blockIdx.x * 16;
    const int t  = threadIdx.x;
    const int dl = t >> 4;
    const int n  = t & 15;
    const int d  = d0 + dl;

    const float Acoef = -__expf((dir ? Alog_b : Alog_f)[d*NST + n]);
    const float DpV   = (dir ? Dp_b : Dp_f)[d];

    __shared__ float sD[32][16], sU[32][16], sZ[32][16], sB2[32][16], sC2[32][16];

    const int la0 = t >> 4, qa0 = t & 15;
    const int la1 = (t + 256) >> 4, qa1 = (t + 256) & 15;

    float rg[10];
    {
        const int lb = (dir == 0) ? 0 : (LSEQ - 32);
        const int row0 = b*LSEQ + lb + la0;
        const int row1 = b*LSEQ + lb + la1;
        rg[0] = g_DELTA[(size_t)row0*4096 + dir*2048 + d0 + qa0];
        rg[1] = g_DELTA[(size_t)row1*4096 + dir*2048 + d0 + qa1];
        rg[2] = g_U[(size_t)row0*4096 + dir*2048 + d0 + qa0];
        rg[3] = g_U[(size_t)row1*4096 + dir*2048 + d0 + qa1];
        rg[4] = g_XZ[(size_t)row0*8192 + dir*4096 + 2048 + d0 + qa0];
        rg[5] = g_XZ[(size_t)row1*8192 + dir*4096 + 2048 + d0 + qa1];
        rg[6] = g_XDBL[(size_t)row0*256 + dir*128 + 64 + qa0];
        rg[7] = g_XDBL[(size_t)row1*256 + dir*128 + 64 + qa1];
        rg[8] = g_XDBL[(size_t)row0*256 + dir*128 + 80 + qa0];
        rg[9] = g_XDBL[(size_t)row1*256 + dir*128 + 80 + qa1];
    }

    float h = 0.f;
    const int NCH = LSEQ / 32;
    for (int c = 0; c < NCH; c++) {
        __syncthreads();
        sD [la0][qa0] = rg[0]; sD [la1][qa1] = rg[1];
        sU [la0][qa0] = rg[2]; sU [la1][qa1] = rg[3];
        sZ [la0][qa0] = rg[4]; sZ [la1][qa1] = rg[5];
        sB2[la0][qa0] = rg[6]; sB2[la1][qa1] = rg[7];
        sC2[la0][qa0] = rg[8]; sC2[la1][qa1] = rg[9];
        __syncthreads();
        if (c + 1 < NCH) {
            const int lb = (dir == 0) ? (c+1)*32 : (LSEQ - (c+2)*32);
            const int row0 = b*LSEQ + lb + la0;
            const int row1 = b*LSEQ + lb + la1;
            rg[0] = g_DELTA[(size_t)row0*4096 + dir*2048 + d0 + qa0];
            rg[1] = g_DELTA[(size_t)row1*4096 + dir*2048 + d0 + qa1];
            rg[2] = g_U[(size_t)row0*4096 + dir*2048 + d0 + qa0];
            rg[3] = g_U[(size_t)row1*4096 + dir*2048 + d0 + qa1];
            rg[4] = g_XZ[(size_t)row0*8192 + dir*4096 + 2048 + d0 + qa0];
            rg[5] = g_XZ[(size_t)row1*8192 + dir*4096 + 2048 + d0 + qa1];
            rg[6] = g_XDBL[(size_t)row0*256 + dir*128 + 64 + qa0];
            rg[7] = g_XDBL[(size_t)row1*256 + dir*128 + 64 + qa1];
            rg[8] = g_XDBL[(size_t)row0*256 + dir*128 + 80 + qa0];
            rg[9] = g_XDBL[(size_t)row1*256 + dir*128 + 80 + qa1];
        }
        const int lb = (dir == 0) ? c*32 : (LSEQ - (c+1)*32);
#pragma unroll 4
        for (int s = 0; s < 32; s++) {
            const int ll = (dir == 0) ? s : (31 - s);
            const float del = sD[ll][dl];
            const float uu  = sU[ll][dl];
            const float dA  = __expf(del * Acoef);
            h = fmaf(h, dA, del * uu * sB2[ll][n]);
            float py = h * sC2[ll][n];
            py += __shfl_xor_sync(0xffffffffu, py, 8);
            py += __shfl_xor_sync(0xffffffffu, py, 4);
            py += __shfl_xor_sync(0xffffffffu, py, 2);
            py += __shfl_xor_sync(0xffffffffu, py, 1);
            if (n == 0) {
                const float zz = sZ[ll][dl];
                const float y = fmaf(uu, DpV, py);
                const float sig = 1.f / (1.f + __expf(-zz));
                const float yg = y * (zz * sig);
                const size_t o = (size_t)(b*LSEQ + lb + ll)*4096 + dir*2048 + d;
                __nv_bfloat16 hh, lo2; split1(yg, hh, lo2);
                g_YGh[o] = hh; g_YGl[o] = lo2;
            }
        }
    }
}

// ------------------------------------ launch ---------------------------------
extern "C" void kernel_launch(void* const* d_in, const int* in_sizes, int n_in,
                              void* d_out, int out_size)
{
    const float* x      = (const float*)d_in[0];
    const float* inW_f  = (const float*)d_in[1];
    const float* convW_f= (const float*)d_in[2];
    const float* convB_f= (const float*)d_in[3];
    const float* xpW_f  = (const float*)d_in[4];
    const float* dtW_f  = (const float*)d_in[5];
    const float* dtB_f  = (const float*)d_in[6];
    const float* Alog_f = (const float*)d_in[7];
    const float* Dp_f   = (const float*)d_in[8];
    const float* outW_f = (const float*)d_in[9];
    const float* inW_b  = (const float*)d_in[10];
    const float* convW_b= (const float*)d_in[11];
    const float* convB_b= (const float*)d_in[12];
    const float* xpW_b  = (const float*)d_in[13];
    const float* dtW_b  = (const float*)d_in[14];
    const float* dtB_b  = (const float*)d_in[15];
    const float* Alog_b = (const float*)d_in[16];
    const float* Dp_b   = (const float*)d_in[17];
    const float* outW_b = (const float*)d_in[18];
    float* out = (float*)d_out;

    float *XZ, *XDBLP, *DELTA;
    __nv_bfloat16 *Xh, *Xl, *Winh, *Winl, *Uh, *Ul, *Xph, *Xpl, *XDh, *XDl;
    __nv_bfloat16 *dtWh, *dtWl, *YGh, *YGl, *Wouth, *Woutl;
    cudaGetSymbolAddress((void**)&XZ,    g_XZ);
    cudaGetSymbolAddress((void**)&XDBLP, g_XDBLP);
    cudaGetSymbolAddress((void**)&DELTA, g_DELTA);
    cudaGetSymbolAddress((void**)&Xh,    g_Xh);
    cudaGetSymbolAddress((void**)&Xl,    g_Xl);
    cudaGetSymbolAddress((void**)&Winh,  g_Winh);
    cudaGetSymbolAddress((void**)&Winl,  g_Winl);
    cudaGetSymbolAddress((void**)&Uh,    g_Uh);
    cudaGetSymbolAddress((void**)&Ul,    g_Ul);
    cudaGetSymbolAddress((void**)&Xph,   g_Xph);
    cudaGetSymbolAddress((void**)&Xpl,   g_Xpl);
    cudaGetSymbolAddress((void**)&XDh,   g_XDh);
    cudaGetSymbolAddress((void**)&XDl,   g_XDl);
    cudaGetSymbolAddress((void**)&dtWh,  g_dtWh);
    cudaGetSymbolAddress((void**)&dtWl,  g_dtWl);
    cudaGetSymbolAddress((void**)&YGh,   g_YGh);
    cudaGetSymbolAddress((void**)&YGl,   g_YGl);
    cudaGetSymbolAddress((void**)&Wouth, g_Wouth);
    cudaGetSymbolAddress((void**)&Woutl, g_Woutl);

    cudaFuncSetAttribute(hgemm<0>, cudaFuncAttributeMaxDynamicSharedMemorySize, HG_SMEM);
    cudaFuncSetAttribute(hgemm<1>, cudaFuncAttributeMaxDynamicSharedMemorySize, HG_SMEM);
    cudaFuncSetAttribute(hgemm<2>, cudaFuncAttributeMaxDynamicSharedMemorySize, HG_SMEM);

    // 0) operand conversions (weights + x)
    cvt_plane<<<2048, 256>>>(x,      Xh,   Xl,   MROWS*DMODEL/4);
    cvt_plane<<<4096, 256>>>(inW_f,  Winh, Winl, 4096*DMODEL/4);
    cvt_plane<<<4096, 256>>>(inW_b,  Winh + 4096*DMODEL, Winl + 4096*DMODEL, 4096*DMODEL/4);
    cvt_plane<<<128,  256>>>(dtW_f,  dtWh, dtWl, 2048*DTR/4);
    cvt_plane<<<128,  256>>>(dtW_b,  dtWh + 2048*DTR, dtWl + 2048*DTR, 2048*DTR/4);
    cvt_xp  <<<512,  256>>>(xpW_f, xpW_b);
    cvt_out <<<4096, 256>>>(outW_f, outW_b);

    // 1) input projection: [2048,8192] = X[2048,1024] * Win[8192,1024]^T
    hgemm<0><<<dim3(64,16,1), 256, HG_SMEM>>>(
        Xh, Xl, DMODEL, 0, 0, Winh, Winl, DMODEL,
        XZ, 8192, DMODEL, nullptr, nullptr, 1.f, 0);

    // 2) depthwise conv + SiLU (emits U fp32 + planes)
    conv_silu_kernel<<<(MROWS*4096)/256, 256>>>(convW_f, convB_f, convW_b, convB_b);

    // 3) x_dbl: [2048,256] = U[.,dir-slice] * Xp[256,2048]^T, split-K=4
    hgemm<0><<<dim3(2,16,4), 256, HG_SMEM>>>(
        Uh, Ul, 4096, 2048, 128, Xph, Xpl, DIN,
        XDBLP, 256, DIN, nullptr, nullptr, 1.f, 512);
    reduce_xdbl_kernel<<<(MROWS*256)/256, 256>>>();

    // 4) delta = softplus(dt @ dtWcat^T + dtB), N=4096, K=64
    hgemm<1><<<dim3(32,16,1), 256, HG_SMEM>>>(
        XDh, XDl, 256, 128, 2048, dtWh, dtWl, DTR,
        DELTA, 4096, DTR, dtB_f, dtB_b, 1.f, 0);

    // 5) selective scan + gating (emits YG planes)
    scan_kernel<<<dim3(128,2,2), 256>>>(Alog_f, Alog_b, Dp_f, Dp_b);

    // 6) out = 0.5 * YG[2048,4096] * Wout[1024,4096]^T (K-concat)
    hgemm<2><<<dim3(8,16,1), 256, HG_SMEM>>>(
        YGh, YGl, 4096, 0, 0, Wouth, Woutl, 4096,
        out, DMODEL, 4096, nullptr, nullptr, 0.5f, 0);
}